// round 6
// baseline (speedup 1.0000x reference)
#include <cuda_runtime.h>
#include <cstdint>
#include <math.h>

#define Bn 8
#define Nn 1024
#define Dn 1024
#define Hn 4096
#define En 16
#define CAP 80
#define MPAD 96
#define SPLITK 4

#define NT 128      // block tile N
#define KT 32       // block tile K

// smem (u32 units), double-buffered:
//   AH [96][20] (k-pairs, row stride 20 for bank spread) = 1920
//   AL [96][20]                                          = 1920
//   BH [16][128] (pair-row p, col n ^ 8*(p&3))           = 2048
//   BL [16][128]                                         = 2048
#define APS 20
#define OFF_AH 0
#define OFF_AL 1920
#define OFF_BH 3840
#define OFF_BL 5888
#define TILE_U32 7936
#define SMEM_BYTES (2 * TILE_U32 * 4)   // 63488

__device__ float g_hidden[(size_t)Bn * MPAD * Hn];
__device__ float g_partial[(size_t)SPLITK * Bn * CAP * Dn];

__device__ __forceinline__ float gelu_exact(float x) {
    return 0.5f * x * (1.0f + erff(x * 0.70710678118654752440f));
}

// Split two f32 into packed bf16x2 hi (truncated) and lo (rounded residual).
__device__ __forceinline__ void split2(float x, float y, uint32_t& hi, uint32_t& lo) {
    uint32_t bx = __float_as_uint(x), by = __float_as_uint(y);
    asm("prmt.b32 %0, %1, %2, 0x7632;" : "=r"(hi) : "r"(bx), "r"(by));
    float lx = x - __uint_as_float(bx & 0xFFFF0000u);
    float ly = y - __uint_as_float(by & 0xFFFF0000u);
    asm("cvt.rn.bf16x2.f32 %0, %1, %2;" : "=r"(lo) : "f"(ly), "f"(lx));
}

__device__ __forceinline__ void mma_bf16(
    float* acc, uint32_t a0, uint32_t a1, uint32_t a2, uint32_t a3,
    uint32_t b0, uint32_t b1)
{
    asm volatile(
        "mma.sync.aligned.m16n8k16.row.col.f32.bf16.bf16.f32 "
        "{%0,%1,%2,%3}, {%4,%5,%6,%7}, {%8,%9}, {%0,%1,%2,%3};"
        : "+f"(acc[0]), "+f"(acc[1]), "+f"(acc[2]), "+f"(acc[3])
        : "r"(a0), "r"(a1), "r"(a2), "r"(a3), "r"(b0), "r"(b1));
}

// ---------------------------------------------------------------------------
// Core: Out[m < mlim, n0:n0+128] = A[96 x K] * B[K x N] over k in
// [kbase, kbase+ktiles*32). 3-term bf16-split mma.sync, fp32 accum.
// 192 threads = 6 warps (3 M x 2 N), warp tile 32x64.
// ---------------------------------------------------------------------------
template <bool GELU>
__device__ __forceinline__ void gemm_core(
    const float* __restrict__ A, int lda,
    const float* __restrict__ Bg, int ldb,
    int n0, int kbase, int ktiles,
    float* __restrict__ Out, int ldo, int mlim)
{
    extern __shared__ uint32_t Sm[];
    const int tid = threadIdx.x;
    const int wid = tid >> 5;
    const int lane = tid & 31;
    const int wm = wid >> 1;        // 0..2
    const int wn = wid & 1;         // 0..1
    const int g = lane >> 2;        // 0..7
    const int c = lane & 3;         // 0..3

    // ---- loader mappings ----
    // A: 96 rows x 8 float4 = 768 float4 -> 4 per thread
    int a_m[4], a_seg[4];
    #pragma unroll
    for (int r = 0; r < 4; r++) {
        int idx = tid + r * 192;
        a_m[r] = idx >> 3;         // row 0..95
        a_seg[r] = idx & 7;        // float4 (2 k-pairs)
    }
    // B: 16 pair-rows x 128 n = 512 float4 -> units tid, tid+192, tid+384(<512)
    int u_p[3], u_n[3], b_dst[3], b_ok[3];
    #pragma unroll
    for (int r = 0; r < 3; r++) {
        int idx = tid + r * 192;
        b_ok[r] = (idx < 512);
        int p = idx >> 5;
        int n = (idx & 31) * 4;
        u_p[r] = p; u_n[r] = n;
        b_dst[r] = p * 128 + (n ^ (8 * (p & 3)));
    }

    float4 areg[4];
    float4 brow0[3], brow1[3];

    float acc[2][8][4];
    #pragma unroll
    for (int f = 0; f < 2; f++)
        #pragma unroll
        for (int j = 0; j < 8; j++)
            #pragma unroll
            for (int i = 0; i < 4; i++) acc[f][j][i] = 0.0f;

    auto ldg_tile = [&](int k0) {
        #pragma unroll
        for (int r = 0; r < 4; r++)
            areg[r] = *reinterpret_cast<const float4*>(
                &A[(size_t)a_m[r] * lda + k0 + a_seg[r] * 4]);
        #pragma unroll
        for (int r = 0; r < 3; r++)
            if (b_ok[r]) {
                const float* bs = Bg + (size_t)(k0 + 2 * u_p[r]) * ldb + n0 + u_n[r];
                brow0[r] = *reinterpret_cast<const float4*>(bs);
                brow1[r] = *reinterpret_cast<const float4*>(bs + ldb);
            }
    };
    auto sts_tile = [&](int buf) {
        uint32_t* base = Sm + buf * TILE_U32;
        #pragma unroll
        for (int r = 0; r < 4; r++) {
            uint32_t h0, l0, h1, l1;
            split2(areg[r].x, areg[r].y, h0, l0);
            split2(areg[r].z, areg[r].w, h1, l1);
            int d = a_m[r] * APS + a_seg[r] * 2;
            *reinterpret_cast<uint2*>(base + OFF_AH + d) = make_uint2(h0, h1);
            *reinterpret_cast<uint2*>(base + OFF_AL + d) = make_uint2(l0, l1);
        }
        #pragma unroll
        for (int r = 0; r < 3; r++)
            if (b_ok[r]) {
                uint32_t h[4], l[4];
                split2(brow0[r].x, brow1[r].x, h[0], l[0]);
                split2(brow0[r].y, brow1[r].y, h[1], l[1]);
                split2(brow0[r].z, brow1[r].z, h[2], l[2]);
                split2(brow0[r].w, brow1[r].w, h[3], l[3]);
                *reinterpret_cast<uint4*>(base + OFF_BH + b_dst[r]) =
                    make_uint4(h[0], h[1], h[2], h[3]);
                *reinterpret_cast<uint4*>(base + OFF_BL + b_dst[r]) =
                    make_uint4(l[0], l[1], l[2], l[3]);
            }
    };

    // ---- prologue ----
    ldg_tile(kbase);
    sts_tile(0);
    if (ktiles > 1) ldg_tile(kbase + KT);
    __syncthreads();

    const int arow0 = (wm * 32 + g) * APS;          // m-frag 0, rows g, g+8
    const int arow1 = arow0 + 8 * APS;
    const int arow2 = arow0 + 16 * APS;             // m-frag 1
    const int arow3 = arow0 + 24 * APS;

    for (int j = 0; j < ktiles; j++) {
        const int buf = j & 1;
        const uint32_t* AH = Sm + buf * TILE_U32 + OFF_AH;
        const uint32_t* AL = Sm + buf * TILE_U32 + OFF_AL;
        const uint32_t* BH = Sm + buf * TILE_U32 + OFF_BH;
        const uint32_t* BL = Sm + buf * TILE_U32 + OFF_BL;

        #pragma unroll
        for (int q = 0; q < 2; q++) {
            const int pa = 8 * q + c;
            uint32_t ah[2][4], al[2][4];
            ah[0][0] = AH[arow0 + pa];     ah[0][1] = AH[arow1 + pa];
            ah[0][2] = AH[arow0 + pa + 4]; ah[0][3] = AH[arow1 + pa + 4];
            ah[1][0] = AH[arow2 + pa];     ah[1][1] = AH[arow3 + pa];
            ah[1][2] = AH[arow2 + pa + 4]; ah[1][3] = AH[arow3 + pa + 4];
            al[0][0] = AL[arow0 + pa];     al[0][1] = AL[arow1 + pa];
            al[0][2] = AL[arow0 + pa + 4]; al[0][3] = AL[arow1 + pa + 4];
            al[1][0] = AL[arow2 + pa];     al[1][1] = AL[arow3 + pa];
            al[1][2] = AL[arow2 + pa + 4]; al[1][3] = AL[arow3 + pa + 4];
            const int pb0 = pa * 128;
            const int pb1 = (pa + 4) * 128;
            #pragma unroll
            for (int jf = 0; jf < 8; jf++) {
                const int nn = (wn * 64 + jf * 8 + g) ^ (8 * c);
                uint32_t bh0 = BH[pb0 + nn], bh1 = BH[pb1 + nn];
                uint32_t bl0 = BL[pb0 + nn], bl1 = BL[pb1 + nn];
                #pragma unroll
                for (int f = 0; f < 2; f++) {
                    mma_bf16(acc[f][jf], ah[f][0], ah[f][1], ah[f][2], ah[f][3], bh0, bh1);
                    mma_bf16(acc[f][jf], ah[f][0], ah[f][1], ah[f][2], ah[f][3], bl0, bl1);
                    mma_bf16(acc[f][jf], al[f][0], al[f][1], al[f][2], al[f][3], bh0, bh1);
                }
            }
        }

        if (j + 1 < ktiles) {
            sts_tile((j + 1) & 1);
            if (j + 2 < ktiles) ldg_tile(kbase + (j + 2) * KT);
        }
        __syncthreads();
    }

    // ---- epilogue ----
    #pragma unroll
    for (int f = 0; f < 2; f++)
        #pragma unroll
        for (int jf = 0; jf < 8; jf++) {
            const int n = n0 + wn * 64 + jf * 8 + 2 * c;
            #pragma unroll
            for (int h = 0; h < 2; h++) {
                const int m = wm * 32 + 16 * f + 8 * h + g;
                if (m < mlim) {
                    float2 v;
                    v.x = acc[f][jf][2 * h + 0];
                    v.y = acc[f][jf][2 * h + 1];
                    if (GELU) { v.x = gelu_exact(v.x); v.y = gelu_exact(v.y); }
                    *reinterpret_cast<float2*>(&Out[(size_t)m * ldo + n]) = v;
                }
            }
        }
}

__global__ __launch_bounds__(192, 2)
void gemm1_kernel(const float* __restrict__ inputs, const int* __restrict__ y,
                  const float* __restrict__ w1)
{
    const int b = blockIdx.y;
    const int e = y[b] % En;
    // reads tokens 0..95 (valid), writes all 96 hidden rows (80..95 unused later)
    gemm_core<true>(inputs + (size_t)b * Nn * Dn, Dn,
                    w1 + (size_t)e * Dn * Hn, Hn,
                    blockIdx.x * NT, 0, Dn / KT,
                    g_hidden + (size_t)b * MPAD * Hn, Hn, MPAD);
}

__global__ __launch_bounds__(192, 2)
void gemm2_kernel(const int* __restrict__ y, const float* __restrict__ w2)
{
    const int b = blockIdx.y;
    const int e = y[b] % En;
    const int split = blockIdx.z;
    gemm_core<false>(g_hidden + (size_t)b * MPAD * Hn, Hn,
                     w2 + (size_t)e * Hn * Dn, Dn,
                     blockIdx.x * NT, split * (Hn / SPLITK), (Hn / SPLITK) / KT,
                     g_partial + ((size_t)split * Bn + b) * CAP * Dn, Dn, CAP);
}

// Sum split-K partials into out for tokens < CAP; zero otherwise.
__global__ __launch_bounds__(256) void reduce_kernel(float* __restrict__ out)
{
    const size_t idx4 = (size_t)blockIdx.x * blockDim.x + threadIdx.x;
    const size_t total4 = (size_t)Bn * Nn * Dn / 4;
    if (idx4 >= total4) return;
    const int per_b4 = Nn * Dn / 4;
    const int b = (int)(idx4 / per_b4);
    const int r = (int)(idx4 % per_b4);
    const int tok = r / (Dn / 4);
    const int d4 = r % (Dn / 4);

    float4 v = make_float4(0.f, 0.f, 0.f, 0.f);
    if (tok < CAP) {
        #pragma unroll
        for (int s = 0; s < SPLITK; s++) {
            const float4 p = *reinterpret_cast<const float4*>(
                &g_partial[(((size_t)s * Bn + b) * CAP + tok) * Dn + d4 * 4]);
            v.x += p.x; v.y += p.y; v.z += p.z; v.w += p.w;
        }
    }
    reinterpret_cast<float4*>(out)[idx4] = v;
}

extern "C" void kernel_launch(void* const* d_in, const int* in_sizes, int n_in,
                              void* d_out, int out_size) {
    const float* inputs = (const float*)d_in[0];   // (8, 1024, 1024) f32
    const int*   y      = (const int*)d_in[1];     // (8,) i32
    const float* w1     = (const float*)d_in[2];   // (16, 1024, 4096) f32
    const float* w2     = (const float*)d_in[3];   // (16, 4096, 1024) f32
    float* out = (float*)d_out;                    // (8, 1024, 1024) f32

    cudaFuncSetAttribute(gemm1_kernel, cudaFuncAttributeMaxDynamicSharedMemorySize, SMEM_BYTES);
    cudaFuncSetAttribute(gemm2_kernel, cudaFuncAttributeMaxDynamicSharedMemorySize, SMEM_BYTES);

    dim3 g1(Hn / NT, Bn);              // 32 x 8 = 256 CTAs
    gemm1_kernel<<<g1, 192, SMEM_BYTES>>>(inputs, y, w1);

    dim3 g2(Dn / NT, Bn, SPLITK);      // 8 x 8 x 4 = 256 CTAs
    gemm2_kernel<<<g2, 192, SMEM_BYTES>>>(y, w2);

    const size_t total4 = (size_t)Bn * Nn * Dn / 4;
    reduce_kernel<<<(unsigned)((total4 + 255) / 256), 256>>>(out);
}